// round 2
// baseline (speedup 1.0000x reference)
#include <cuda_runtime.h>

#define N_NODES 50000
#define N_EDGES 640000
// IN_DIM = OUT_DIM = 128, H = 4, D = 32

// ---------------- scratch (device globals; no allocation allowed) ------------
__device__ __align__(16) float g_Wh[N_NODES * 128];
__device__ __align__(16) float g_sl[N_NODES * 4];
__device__ __align__(16) float g_sr[N_NODES * 4];
__device__ __align__(16) float g_attn[N_EDGES * 4];
__device__ __align__(16) float g_maxv[N_NODES * 4];
__device__ __align__(16) float g_denom[N_NODES * 4];

// CAS-free float atomic max (monotone-bits trick: int-max for >=0, uint-min for <0)
__device__ __forceinline__ void atomicMaxFloat(float* addr, float v) {
    if (v >= 0.0f)
        atomicMax((int*)addr, __float_as_int(v));
    else
        atomicMin((unsigned int*)addr, __float_as_uint(v));
}

// ---------------- K0: init agg buffer / maxv / denom ------------------------
__global__ void k_init(float* __restrict__ out) {
    int i = blockIdx.x * blockDim.x + threadIdx.x;
    if (i < N_NODES * 128) out[i] = 0.0f;
    if (i < N_NODES * 4) {
        g_maxv[i]  = -1e9f;
        g_denom[i] = 0.0f;
    }
}

// ---------------- K1: Wh = h @ W^T, plus s_l / s_r epilogue ------------------
// block = 256 threads (8 warps). Each warp: 4 rows. Lane: cols c = lane + 32*j
// (so j == head index, lane == dim-within-head). W^T staged in shared in two
// k-phases of 64 (padded to 133 floats/row -> conflict-free both ways).
__global__ void __launch_bounds__(256) k_gemm(const float* __restrict__ h,
                                              const float* __restrict__ W,
                                              const float* __restrict__ a) {
    __shared__ float Ws[64 * 133];
    const int tid  = threadIdx.x;
    const int lane = tid & 31;
    const int warp = tid >> 5;
    const int rowbase = blockIdx.x * 32 + warp * 4;

    float acc[4][4];
#pragma unroll
    for (int r = 0; r < 4; r++)
#pragma unroll
        for (int j = 0; j < 4; j++) acc[r][j] = 0.0f;

    // attention vectors: a[h][0:32] (src half), a[h][32:64] (dst half)
    float al[4], ar[4];
#pragma unroll
    for (int j = 0; j < 4; j++) {
        al[j] = a[j * 64 + lane];
        ar[j] = a[j * 64 + 32 + lane];
    }

    const float4* h4 = reinterpret_cast<const float4*>(h);

    for (int p = 0; p < 2; p++) {
        __syncthreads();
        // Ws[k][c] = W[c][p*64 + k]  (coalesced global read, padded smem write)
        for (int i = tid; i < 128 * 64; i += 256) {
            int c = i >> 6;
            int k = i & 63;
            Ws[k * 133 + c] = W[c * 128 + p * 64 + k];
        }
        __syncthreads();

#pragma unroll 1
        for (int k4 = 0; k4 < 16; k4++) {
            float4 hv[4];
#pragma unroll
            for (int r = 0; r < 4; r++) {
                int row = rowbase + r;
                int rr  = row < N_NODES ? row : N_NODES - 1;
                hv[r] = h4[rr * 32 + p * 16 + k4];
            }
#pragma unroll
            for (int kk = 0; kk < 4; kk++) {
                int k = k4 * 4 + kk;
                float w0 = Ws[k * 133 + lane];
                float w1 = Ws[k * 133 + lane + 32];
                float w2 = Ws[k * 133 + lane + 64];
                float w3 = Ws[k * 133 + lane + 96];
#pragma unroll
                for (int r = 0; r < 4; r++) {
                    float hk = (kk == 0) ? hv[r].x : (kk == 1) ? hv[r].y
                             : (kk == 2) ? hv[r].z : hv[r].w;
                    acc[r][0] += hk * w0;
                    acc[r][1] += hk * w1;
                    acc[r][2] += hk * w2;
                    acc[r][3] += hk * w3;
                }
            }
        }
    }

    // epilogue: store Wh; warp-reduce s_l/s_r per head
#pragma unroll
    for (int r = 0; r < 4; r++) {
        int row = rowbase + r;
        if (row >= N_NODES) break;
#pragma unroll
        for (int j = 0; j < 4; j++)
            g_Wh[row * 128 + j * 32 + lane] = acc[r][j];
#pragma unroll
        for (int j = 0; j < 4; j++) {
            float pl = acc[r][j] * al[j];
            float pr = acc[r][j] * ar[j];
#pragma unroll
            for (int o = 16; o > 0; o >>= 1) {
                pl += __shfl_xor_sync(0xffffffffu, pl, o);
                pr += __shfl_xor_sync(0xffffffffu, pr, o);
            }
            if (lane == 0) {
                g_sl[row * 4 + j] = pl;
                g_sr[row * 4 + j] = pr;
            }
        }
    }
}

// ---------------- K2: per-edge attention logits + scatter max ---------------
__global__ void __launch_bounds__(256) k_attn(const int* __restrict__ ei,
                                              const float* __restrict__ ef,
                                              const float* __restrict__ We) {
    __shared__ float sWe[64];
    if (threadIdx.x < 64) sWe[threadIdx.x] = We[threadIdx.x];
    __syncthreads();

    int e = blockIdx.x * blockDim.x + threadIdx.x;
    if (e >= N_EDGES) return;

    int s = ei[e];
    int d = ei[N_EDGES + e];

    float4 l4 = *reinterpret_cast<const float4*>(&g_sl[s * 4]);
    float4 r4 = *reinterpret_cast<const float4*>(&g_sr[d * 4]);
    float lv[4] = {l4.x, l4.y, l4.z, l4.w};
    float rv[4] = {r4.x, r4.y, r4.z, r4.w};

    float efv[16];
    const float4* ef4 = reinterpret_cast<const float4*>(ef + (size_t)e * 16);
#pragma unroll
    for (int q = 0; q < 4; q++) {
        float4 t = ef4[q];
        efv[q * 4 + 0] = t.x; efv[q * 4 + 1] = t.y;
        efv[q * 4 + 2] = t.z; efv[q * 4 + 3] = t.w;
    }

    float att[4];
#pragma unroll
    for (int hh = 0; hh < 4; hh++) {
        float x = lv[hh] + rv[hh];
        x = x > 0.0f ? x : 0.2f * x;           // leaky_relu(slope=0.2)
        float dot = 0.0f;
#pragma unroll
        for (int q = 0; q < 16; q++) dot += efv[q] * sWe[hh * 16 + q];
        att[hh] = x + dot;
        atomicMaxFloat(&g_maxv[d * 4 + hh], att[hh]);
    }
    *reinterpret_cast<float4*>(&g_attn[e * 4]) =
        make_float4(att[0], att[1], att[2], att[3]);
}

// ---------------- K3: exp + denom + weighted scatter-add (warp per edge) ----
__global__ void __launch_bounds__(256) k_agg(const int* __restrict__ ei,
                                             float* __restrict__ out) {
    int gw   = (blockIdx.x * blockDim.x + threadIdx.x) >> 5;
    int lane = threadIdx.x & 31;
    if (gw >= N_EDGES) return;

    int s = ei[gw];                   // lane-uniform -> broadcast load
    int d = ei[N_EDGES + gw];

    float4 at = *reinterpret_cast<const float4*>(&g_attn[gw * 4]);
    float4 mv = *reinterpret_cast<const float4*>(&g_maxv[d * 4]);
    float e0 = __expf(at.x - mv.x);
    float e1 = __expf(at.y - mv.y);
    float e2 = __expf(at.z - mv.z);
    float e3 = __expf(at.w - mv.w);

    if (lane < 4) {
        float exh = (lane == 0) ? e0 : (lane == 1) ? e1 : (lane == 2) ? e2 : e3;
        atomicAdd(&g_denom[d * 4 + lane], exh);
    }

    // lane covers cols 4*lane..4*lane+3 ; head = lane/8
    float4 v = reinterpret_cast<const float4*>(&g_Wh[(size_t)s * 128])[lane];
    int head = lane >> 3;
    float sc = (head == 0) ? e0 : (head == 1) ? e1 : (head == 2) ? e2 : e3;
    float r0 = v.x * sc, r1 = v.y * sc, r2 = v.z * sc, r3 = v.w * sc;

    float* addr = out + (size_t)d * 128 + lane * 4;
    asm volatile("red.global.add.v4.f32 [%0], {%1,%2,%3,%4};"
                 :: "l"(addr), "f"(r0), "f"(r1), "f"(r2), "f"(r3)
                 : "memory");
}

// ---------------- K4: normalize + GELU(exact) + LayerNorm (warp per node) ---
__global__ void __launch_bounds__(256) k_final(const float* __restrict__ ln_s,
                                               const float* __restrict__ ln_b,
                                               float* __restrict__ out) {
    int gw   = (blockIdx.x * blockDim.x + threadIdx.x) >> 5;
    int lane = threadIdx.x & 31;
    if (gw >= N_NODES) return;

    int head  = lane >> 3;
    float den = g_denom[gw * 4 + head] + 1e-9f;
    float inv = 1.0f / den;

    float4 v = reinterpret_cast<float4*>(out + (size_t)gw * 128)[lane];
    float x0 = v.x * inv, x1 = v.y * inv, x2 = v.z * inv, x3 = v.w * inv;

    // exact GELU: 0.5*x*(1+erf(x/sqrt(2)))
    const float k = 0.70710678118654752f;
    x0 = 0.5f * x0 * (1.0f + erff(x0 * k));
    x1 = 0.5f * x1 * (1.0f + erff(x1 * k));
    x2 = 0.5f * x2 * (1.0f + erff(x2 * k));
    x3 = 0.5f * x3 * (1.0f + erff(x3 * k));

    // mean over 128
    float ssum = x0 + x1 + x2 + x3;
#pragma unroll
    for (int o = 16; o > 0; o >>= 1) ssum += __shfl_xor_sync(0xffffffffu, ssum, o);
    float mu = ssum * (1.0f / 128.0f);

    float c0 = x0 - mu, c1 = x1 - mu, c2 = x2 - mu, c3 = x3 - mu;
    float vsum = c0 * c0 + c1 * c1 + c2 * c2 + c3 * c3;
#pragma unroll
    for (int o = 16; o > 0; o >>= 1) vsum += __shfl_xor_sync(0xffffffffu, vsum, o);
    float rstd = rsqrtf(vsum * (1.0f / 128.0f) + 1e-5f);

    float4 g = reinterpret_cast<const float4*>(ln_s)[lane];
    float4 b = reinterpret_cast<const float4*>(ln_b)[lane];
    float4 o4;
    o4.x = c0 * rstd * g.x + b.x;
    o4.y = c1 * rstd * g.y + b.y;
    o4.z = c2 * rstd * g.z + b.z;
    o4.w = c3 * rstd * g.w + b.w;
    reinterpret_cast<float4*>(out + (size_t)gw * 128)[lane] = o4;
}

// ---------------- launch -----------------------------------------------------
extern "C" void kernel_launch(void* const* d_in, const int* in_sizes, int n_in,
                              void* d_out, int out_size) {
    const float* h    = (const float*)d_in[0];
    const int*   ei   = (const int*)d_in[1];
    const float* ef   = (const float*)d_in[2];
    const float* W    = (const float*)d_in[3];
    const float* We   = (const float*)d_in[4];
    const float* a    = (const float*)d_in[5];
    const float* ln_s = (const float*)d_in[6];
    const float* ln_b = (const float*)d_in[7];
    float* out = (float*)d_out;

    k_init<<<(N_NODES * 128 + 255) / 256, 256>>>(out);
    k_gemm<<<(N_NODES + 31) / 32, 256>>>(h, W, a);
    k_attn<<<(N_EDGES + 255) / 256, 256>>>(ei, ef, We);
    k_agg<<<(N_EDGES * 32 + 255) / 256, 256>>>(ei, out);
    k_final<<<(N_NODES * 32 + 255) / 256, 256>>>(ln_s, ln_b, out);
}